// round 1
// baseline (speedup 1.0000x reference)
#include <cuda_runtime.h>
#include <math.h>

// ConvergedInhibition == circular deconvolution along C=128 channels.
// Reduced to Y = G @ X, G[r][j] = g[(r-j)&127], g = ifft(1/fft(delta-k)).
// Step 1: tiny prep kernel computes g (direct DFT, 27 filter taps).
// Step 2: fp32 GEMM using packed fma.rn.f32x2 (FFMA2, sm_10x 2x fp32 rate).

#define CCH    128
#define HWSZ   4096
#define NBATCH 64
#define SCOPE  27
#define TILE_N 128
#define GS_PITCH 132                                // floats; 16B-aligned rows
#define SMEM_GS  (CCH * GS_PITCH * 4)               // 67584 B
#define SMEM_XS  (CCH * TILE_N * 4)                 // 65536 B
#define SMEM_TOTAL (SMEM_GS + SMEM_XS)              // 133120 B

__device__ float g_vec[CCH];

// ---------------------------------------------------------------------------
// Prep: g[c] = (1/128) * Re( sum_f e^{+2pi i f c/128} / Fk[f] ),
// Fk[f] = 1 - sum_{j<27} filt[j] * e^{-2pi i f p_j/128}, p_j = (115+j)&127
// (pad_left=50, roll by C/2+1=65  =>  k[(50+j+65)&127] = filt[j]).
// ---------------------------------------------------------------------------
__global__ void prep_kernel(const float* __restrict__ filt) {
    __shared__ float tw_re[CCH], tw_im[CCH];
    __shared__ float inv_re[CCH], inv_im[CCH];
    __shared__ float ft[SCOPE];
    int t = threadIdx.x;  // 0..127
    if (t < SCOPE) ft[t] = filt[t];
    float s, c;
    sincosf(6.283185307179586f * (float)t / 128.0f, &s, &c);
    tw_re[t] = c;
    tw_im[t] = s;
    __syncthreads();

    float fr = 1.0f, fi = 0.0f;
#pragma unroll
    for (int j = 0; j < SCOPE; j++) {
        int p   = (115 + j) & 127;
        int idx = (t * p) & 127;
        // e^{-i theta}: re = cos, im = -sin
        fr -= ft[j] * tw_re[idx];
        fi += ft[j] * tw_im[idx];
    }
    float d = fr * fr + fi * fi;
    inv_re[t] = fr / d;
    inv_im[t] = -fi / d;
    __syncthreads();

    float acc = 0.0f;
    for (int f = 0; f < CCH; f++) {
        int idx = (f * t) & 127;
        acc += tw_re[idx] * inv_re[f] - tw_im[idx] * inv_im[f];
    }
    g_vec[t] = acc * (1.0f / 128.0f);
}

// ---------------------------------------------------------------------------
// Packed fp32 helpers (sm_10x f32x2 pipe: 2 FMAs per FFMA2 issue)
// ---------------------------------------------------------------------------
__device__ __forceinline__ unsigned long long dup2(float v) {
    unsigned long long r;
    asm("mov.b64 %0, {%1, %1};" : "=l"(r) : "f"(v));
    return r;
}
__device__ __forceinline__ void ffma2(unsigned long long& d,
                                      unsigned long long a,
                                      unsigned long long b) {
    asm("fma.rn.f32x2 %0, %1, %2, %0;" : "+l"(d) : "l"(a), "l"(b));
}

// ---------------------------------------------------------------------------
// GEMM: per block, one batch n and one 128-column spatial tile.
// Output tile 128 (all channels) x 128 cols; 256 threads, 8x8 micro-tile,
// columns packed in pairs for FFMA2.
// ---------------------------------------------------------------------------
__global__ void __launch_bounds__(256, 1)
gemm_kernel(const float* __restrict__ x, float* __restrict__ y) {
    extern __shared__ float smem[];
    float* Gs = smem;                       // [128][GS_PITCH]
    float* Xs = smem + CCH * GS_PITCH;      // [128][TILE_N]
    __shared__ float gsh[CCH];

    int tid  = threadIdx.x;
    int n    = blockIdx.y;
    int col0 = blockIdx.x * TILE_N;
    const float* xb = x + (size_t)n * CCH * HWSZ + col0;
    float*       yb = y + (size_t)n * CCH * HWSZ + col0;

    if (tid < CCH) gsh[tid] = g_vec[tid];
    __syncthreads();

    // Expand G into SMEM: Gs[r][k] = g[(r-k)&127]
#pragma unroll
    for (int t = 0; t < 64; t++) {
        int idx = tid + t * 256;            // 0..16383
        int r = idx >> 7, k = idx & 127;
        Gs[r * GS_PITCH + k] = gsh[(r - k) & 127];
    }
    // Load X tile (128 rows x 128 cols) with float4, coalesced
#pragma unroll
    for (int t = 0; t < 16; t++) {
        int i   = tid + t * 256;            // 0..4095 float4s
        int row = i >> 5;
        int c4  = i & 31;
        float4 v = *reinterpret_cast<const float4*>(xb + (size_t)row * HWSZ + c4 * 4);
        *reinterpret_cast<float4*>(&Xs[row * TILE_N + c4 * 4]) = v;
    }
    __syncthreads();

    int tx = tid & 15;   // columns tx*8 .. tx*8+7
    int ty = tid >> 4;   // rows    ty*8 .. ty*8+7
    const float* GsBase = &Gs[(ty * 8) * GS_PITCH];
    const float* XsBase = &Xs[tx * 8];

    unsigned long long acc[8][4];
#pragma unroll
    for (int r = 0; r < 8; r++)
#pragma unroll
        for (int c = 0; c < 4; c++) acc[r][c] = 0ULL;

    for (int k0 = 0; k0 < CCH; k0 += 4) {
        float4 g4[8];
#pragma unroll
        for (int r = 0; r < 8; r++)
            g4[r] = *reinterpret_cast<const float4*>(GsBase + r * GS_PITCH + k0);
#pragma unroll
        for (int kk = 0; kk < 4; kk++) {
            const float* xr = XsBase + (k0 + kk) * TILE_N;
            ulonglong2 xa  = *reinterpret_cast<const ulonglong2*>(xr);
            ulonglong2 xb2 = *reinterpret_cast<const ulonglong2*>(xr + 4);
            unsigned long long xv0 = xa.x, xv1 = xa.y, xv2 = xb2.x, xv3 = xb2.y;
#pragma unroll
            for (int r = 0; r < 8; r++) {
                float gs = (kk == 0) ? g4[r].x : (kk == 1) ? g4[r].y
                          : (kk == 2) ? g4[r].z : g4[r].w;
                unsigned long long gd = dup2(gs);
                ffma2(acc[r][0], gd, xv0);
                ffma2(acc[r][1], gd, xv1);
                ffma2(acc[r][2], gd, xv2);
                ffma2(acc[r][3], gd, xv3);
            }
        }
    }

#pragma unroll
    for (int r = 0; r < 8; r++) {
        float* yr = yb + (size_t)(ty * 8 + r) * HWSZ + tx * 8;
        ulonglong2 v0, v1;
        v0.x = acc[r][0]; v0.y = acc[r][1];
        v1.x = acc[r][2]; v1.y = acc[r][3];
        *reinterpret_cast<ulonglong2*>(yr)     = v0;
        *reinterpret_cast<ulonglong2*>(yr + 4) = v1;
    }
}

// ---------------------------------------------------------------------------
extern "C" void kernel_launch(void* const* d_in, const int* in_sizes, int n_in,
                              void* d_out, int out_size) {
    const float* act  = (const float*)d_in[0];
    const float* filt = (const float*)d_in[1];
    if (n_in >= 2 && in_sizes[0] == SCOPE) {  // defensive: swap if order differs
        act  = (const float*)d_in[1];
        filt = (const float*)d_in[0];
    }
    float* out = (float*)d_out;

    prep_kernel<<<1, 128>>>(filt);

    cudaFuncSetAttribute(gemm_kernel,
                         cudaFuncAttributeMaxDynamicSharedMemorySize, SMEM_TOTAL);
    dim3 grid(HWSZ / TILE_N, NBATCH);
    gemm_kernel<<<grid, 256, SMEM_TOTAL>>>(act, out);
}

// round 3
// speedup vs baseline: 2.6937x; 2.6937x over previous
#include <cuda_runtime.h>
#include <cuda_bf16.h>
#include <cstdint>
#include <math.h>

// ConvergedInhibition == circular deconvolution along C=128 channels.
// Y = G @ X, G[r][j] = g[(r-j)&127], g = ifft(1/fft(delta-k)).
// R3: portable tensor cores (mma.sync m16n8k16 bf16 -> HMMA on sm_103 base),
// error-compensated split: Y = Gh@Xh + Gl@Xh + Gh@Xl.
// A(G) mma fragments precomputed in gmem by prep (same for every CTA).

#define CCH     128
#define HWSZ    4096
#define NBATCH  64
#define SCOPE   27
#define NTILE   128
#define NTHREADS 256

#define XPITCH_B 272                       // bytes per n-row (17*16B)
#define SMEM_XH  0
#define SMEM_XL  (NTILE * XPITCH_B)        // 34816
#define SMEM_DYN (2 * NTILE * XPITCH_B)    // 69632

__device__ float g_vec[CCH];
__device__ uint4 a_frag_h[8 * 8 * 32];     // [mtile][kstep][lane], 32KB
__device__ uint4 a_frag_l[8 * 8 * 32];

// ---------------------------------------------------------------------------
__device__ __forceinline__ uint32_t s2u(const void* p) {
    uint32_t a;
    asm("{ .reg .u64 t; cvta.to.shared.u64 t, %1; cvt.u32.u64 %0, t; }"
        : "=r"(a) : "l"(p));
    return a;
}
__device__ __forceinline__ uint32_t pack_bf16x2(float lo, float hi) {
    uint32_t r;
    asm("cvt.rn.bf16x2.f32 %0, %1, %2;" : "=r"(r) : "f"(hi), "f"(lo));
    return r;
}
__device__ __forceinline__ void ldsm_x4(uint32_t& r0, uint32_t& r1,
                                        uint32_t& r2, uint32_t& r3, uint32_t a) {
    asm volatile("ldmatrix.sync.aligned.m8n8.x4.shared.b16 {%0,%1,%2,%3}, [%4];"
                 : "=r"(r0), "=r"(r1), "=r"(r2), "=r"(r3) : "r"(a));
}
__device__ __forceinline__ void mma16816(float* c, const uint4& a,
                                         uint32_t b0, uint32_t b1) {
    asm volatile(
        "mma.sync.aligned.m16n8k16.row.col.f32.bf16.bf16.f32 "
        "{%0,%1,%2,%3}, {%4,%5,%6,%7}, {%8,%9}, {%0,%1,%2,%3};"
        : "+f"(c[0]), "+f"(c[1]), "+f"(c[2]), "+f"(c[3])
        : "r"(a.x), "r"(a.y), "r"(a.z), "r"(a.w), "r"(b0), "r"(b1));
}

// ---------------------------------------------------------------------------
// Prep: compute g (validated R1), then write A-fragment tables (hi/lo bf16).
// Fragment reg pairs for mma m16n8k16 A (row-major):
//   r0:(m,k) r1:(m+8,k) r2:(m,k+8) r3:(m+8,k+8), each = bf16x2 of (k, k+1).
// ---------------------------------------------------------------------------
__global__ void prep_kernel(const float* __restrict__ filt) {
    __shared__ float tw_re[CCH], tw_im[CCH];
    __shared__ float inv_re[CCH], inv_im[CCH];
    __shared__ float ft[SCOPE];
    __shared__ float gh_s[CCH], gl_s[CCH];
    int t = threadIdx.x;   // 0..255
    if (t < SCOPE) ft[t] = filt[t];
    if (t < CCH) {
        float s, c;
        sincosf(6.283185307179586f * (float)t / 128.0f, &s, &c);
        tw_re[t] = c; tw_im[t] = s;
    }
    __syncthreads();
    if (t < CCH) {
        float fr = 1.0f, fi = 0.0f;
#pragma unroll
        for (int j = 0; j < SCOPE; j++) {
            int p = (115 + j) & 127;
            int idx = (t * p) & 127;
            fr -= ft[j] * tw_re[idx];
            fi += ft[j] * tw_im[idx];
        }
        float d = fr * fr + fi * fi;
        inv_re[t] = fr / d; inv_im[t] = -fi / d;
    }
    __syncthreads();
    if (t < CCH) {
        float acc = 0.0f;
        for (int f = 0; f < CCH; f++) {
            int idx = (f * t) & 127;
            acc += tw_re[idx] * inv_re[f] - tw_im[idx] * inv_im[f];
        }
        float g = acc * (1.0f / 128.0f);
        g_vec[t] = g;
        __nv_bfloat16 gh = __float2bfloat16(g);
        gh_s[t] = __bfloat162float(gh);
        gl_s[t] = g - gh_s[t];
    }
    __syncthreads();

    // A-fragment tables: 2048 lane-entries, 8 per thread.
    for (int e = t; e < 8 * 8 * 32; e += 256) {
        int lane = e & 31;
        int ks   = (e >> 5) & 7;
        int mt   = e >> 8;
        int m = mt * 16 + (lane >> 2);
        int k = ks * 16 + 2 * (lane & 3);
        uint4 h, l;
        int d0 = (m - k) & 127;
        h.x = pack_bf16x2(gh_s[d0], gh_s[(d0 - 1) & 127]);
        l.x = pack_bf16x2(gl_s[d0], gl_s[(d0 - 1) & 127]);
        int d1 = (m + 8 - k) & 127;
        h.y = pack_bf16x2(gh_s[d1], gh_s[(d1 - 1) & 127]);
        l.y = pack_bf16x2(gl_s[d1], gl_s[(d1 - 1) & 127]);
        int d2 = (m - k - 8) & 127;
        h.z = pack_bf16x2(gh_s[d2], gh_s[(d2 - 1) & 127]);
        l.z = pack_bf16x2(gl_s[d2], gl_s[(d2 - 1) & 127]);
        int d3 = d0;  // (m+8)-(k+8)
        h.w = h.x;
        l.w = l.x;
        (void)d3;
        a_frag_h[e] = h;
        a_frag_l[e] = l;
    }
}

// ---------------------------------------------------------------------------
// GEMM: one CTA = 128 out-channels x 128 spatial cols, K=128.
// 8 warps: warp_m = wid&3 (32 rows), warp_n = wid>>2 (64 cols).
// ---------------------------------------------------------------------------
__global__ void __launch_bounds__(NTHREADS, 2)
gemm_mma(const float* __restrict__ x, float* __restrict__ y) {
    extern __shared__ char smc[];
    const int tid  = threadIdx.x;
    const int wid  = tid >> 5;
    const int lane = tid & 31;
    const int warp_m = wid & 3;
    const int warp_n = wid >> 2;

    const int b     = blockIdx.x;
    const int batch = b >> 5;
    const int col0  = (b & 31) * NTILE;
    const float* xb = x + (size_t)batch * CCH * HWSZ + col0;
    float*       yb = y + (size_t)batch * CCH * HWSZ + col0;

    // ---- Load X tile, split to bf16 hi/lo, transpose into Bs[n][k] ----
#pragma unroll
    for (int it = 0; it < 16; it++) {
        int idx = tid + it * 256;          // 0..4095
        int n   = idx & 127;
        int kq  = idx >> 7;                // 0..31 (4 k's each)
        const float* p = xb + (size_t)(kq * 4) * HWSZ + n;
        float v0 = __ldg(p);
        float v1 = __ldg(p + HWSZ);
        float v2 = __ldg(p + 2 * HWSZ);
        float v3 = __ldg(p + 3 * HWSZ);
        float h0 = __bfloat162float(__float2bfloat16(v0));
        float h1 = __bfloat162float(__float2bfloat16(v1));
        float h2 = __bfloat162float(__float2bfloat16(v2));
        float h3 = __bfloat162float(__float2bfloat16(v3));
        uint2 hi, lo;
        hi.x = pack_bf16x2(v0, v1);
        hi.y = pack_bf16x2(v2, v3);
        lo.x = pack_bf16x2(v0 - h0, v1 - h1);
        lo.y = pack_bf16x2(v2 - h2, v3 - h3);
        uint32_t off = (uint32_t)n * XPITCH_B + kq * 8;
        *reinterpret_cast<uint2*>(smc + SMEM_XH + off) = hi;
        *reinterpret_cast<uint2*>(smc + SMEM_XL + off) = lo;
    }
    __syncthreads();

    // ---- MMA mainloop ----
    float acc[2][8][4];
#pragma unroll
    for (int mt = 0; mt < 2; mt++)
#pragma unroll
        for (int nt = 0; nt < 8; nt++)
#pragma unroll
            for (int r = 0; r < 4; r++) acc[mt][nt][r] = 0.0f;

    // per-lane ldmatrix offset: rows (lane&7) + 8*(lane>=16), k-half (lane>>3)&1
    const uint32_t lm_off = ((lane & 7) + ((lane >> 4) << 3)) * XPITCH_B
                          + ((lane >> 3) & 1) * 16;
    const uint32_t xh_base = s2u(smc) + SMEM_XH + (uint32_t)warp_n * 64 * XPITCH_B + lm_off;
    const uint32_t xl_base = xh_base + SMEM_XL;
    const int fbase = (warp_m * 2) * 8 * 32 + lane;  // mtile 0 of this warp

#pragma unroll
    for (int ks = 0; ks < 8; ks++) {
        uint4 ah0 = a_frag_h[fbase + ks * 32];
        uint4 ah1 = a_frag_h[fbase + (8 + ks) * 32];
        uint4 al0 = a_frag_l[fbase + ks * 32];
        uint4 al1 = a_frag_l[fbase + (8 + ks) * 32];
        uint32_t kofs = ks * 32;
#pragma unroll
        for (int p = 0; p < 4; p++) {
            uint32_t bh0, bh1, bh2, bh3, bl0, bl1, bl2, bl3;
            ldsm_x4(bh0, bh1, bh2, bh3, xh_base + p * (16 * XPITCH_B) + kofs);
            ldsm_x4(bl0, bl1, bl2, bl3, xl_base + p * (16 * XPITCH_B) + kofs);
            // ntile 2p: (bh0,bh1); ntile 2p+1: (bh2,bh3)
            mma16816(acc[0][2 * p],     ah0, bh0, bh1);
            mma16816(acc[1][2 * p],     ah1, bh0, bh1);
            mma16816(acc[0][2 * p + 1], ah0, bh2, bh3);
            mma16816(acc[1][2 * p + 1], ah1, bh2, bh3);
            mma16816(acc[0][2 * p],     al0, bh0, bh1);
            mma16816(acc[1][2 * p],     al1, bh0, bh1);
            mma16816(acc[0][2 * p + 1], al0, bh2, bh3);
            mma16816(acc[1][2 * p + 1], al1, bh2, bh3);
            mma16816(acc[0][2 * p],     ah0, bl0, bl1);
            mma16816(acc[1][2 * p],     ah1, bl0, bl1);
            mma16816(acc[0][2 * p + 1], ah0, bl2, bl3);
            mma16816(acc[1][2 * p + 1], ah1, bl2, bl3);
        }
    }

    // ---- Epilogue: c0,c1 at (m=lane/4, n=2*(lane&3)); c2,c3 at m+8 ----
#pragma unroll
    for (int mt = 0; mt < 2; mt++) {
        int m0 = warp_m * 32 + mt * 16 + (lane >> 2);
        float* yr0 = yb + (size_t)m0 * HWSZ;
        float* yr8 = yr0 + (size_t)8 * HWSZ;
#pragma unroll
        for (int nt = 0; nt < 8; nt++) {
            int n = warp_n * 64 + nt * 8 + 2 * (lane & 3);
            float2 v0 = make_float2(acc[mt][nt][0], acc[mt][nt][1]);
            float2 v1 = make_float2(acc[mt][nt][2], acc[mt][nt][3]);
            *reinterpret_cast<float2*>(yr0 + n) = v0;
            *reinterpret_cast<float2*>(yr8 + n) = v1;
        }
    }
}

// ---------------------------------------------------------------------------
extern "C" void kernel_launch(void* const* d_in, const int* in_sizes, int n_in,
                              void* d_out, int out_size) {
    const float* act  = (const float*)d_in[0];
    const float* filt = (const float*)d_in[1];
    if (n_in >= 2 && in_sizes[0] == SCOPE) {
        act  = (const float*)d_in[1];
        filt = (const float*)d_in[0];
    }
    float* out = (float*)d_out;

    prep_kernel<<<1, 256>>>(filt);

    cudaFuncSetAttribute(gemm_mma,
                         cudaFuncAttributeMaxDynamicSharedMemorySize, SMEM_DYN);
    gemm_mma<<<NBATCH * (HWSZ / NTILE), NTHREADS, SMEM_DYN>>>(act, out);
}

// round 4
// speedup vs baseline: 2.8014x; 1.0400x over previous
#include <cuda_runtime.h>
#include <cuda_bf16.h>
#include <cstdint>
#include <math.h>

// ConvergedInhibition == circular deconvolution along C=128 channels.
// Y = G @ X, G[r][j] = g[(r-j)&127], g = ifft(1/fft(delta-k)).
// R4: mma.sync bf16 3-pass split (R3) + conflict-free STS.128 load phase
//     + cheap truncation-based hi/lo split (PRMT + masked-sub).

#define CCH     128
#define HWSZ    4096
#define NBATCH  64
#define SCOPE   27
#define NTILE   128
#define NTHREADS 256

#define XPITCH_B 272                       // bytes per n-row (17*16B)
#define SMEM_XH  0
#define SMEM_XL  (NTILE * XPITCH_B)        // 34816
#define SMEM_DYN (2 * NTILE * XPITCH_B)    // 69632

__device__ float g_vec[CCH];
__device__ uint4 a_frag_h[8 * 8 * 32];     // [mtile][kstep][lane], 32KB
__device__ uint4 a_frag_l[8 * 8 * 32];

// ---------------------------------------------------------------------------
__device__ __forceinline__ uint32_t s2u(const void* p) {
    uint32_t a;
    asm("{ .reg .u64 t; cvta.to.shared.u64 t, %1; cvt.u32.u64 %0, t; }"
        : "=r"(a) : "l"(p));
    return a;
}
__device__ __forceinline__ uint32_t pack_bf16x2(float lo, float hi) {
    uint32_t r;
    asm("cvt.rn.bf16x2.f32 %0, %1, %2;" : "=r"(r) : "f"(hi), "f"(lo));
    return r;
}
__device__ __forceinline__ uint32_t prmt_hi16(uint32_t a, uint32_t b) {
    // result = [a.hi16 (lo half), b.hi16 (hi half)] -> bf16x2 (trunc round)
    uint32_t r;
    asm("prmt.b32 %0, %1, %2, 0x7632;" : "=r"(r) : "r"(a), "r"(b));
    return r;
}
__device__ __forceinline__ void ldsm_x4(uint32_t& r0, uint32_t& r1,
                                        uint32_t& r2, uint32_t& r3, uint32_t a) {
    asm volatile("ldmatrix.sync.aligned.m8n8.x4.shared.b16 {%0,%1,%2,%3}, [%4];"
                 : "=r"(r0), "=r"(r1), "=r"(r2), "=r"(r3) : "r"(a));
}
__device__ __forceinline__ void mma16816(float* c, const uint4& a,
                                         uint32_t b0, uint32_t b1) {
    asm volatile(
        "mma.sync.aligned.m16n8k16.row.col.f32.bf16.bf16.f32 "
        "{%0,%1,%2,%3}, {%4,%5,%6,%7}, {%8,%9}, {%0,%1,%2,%3};"
        : "+f"(c[0]), "+f"(c[1]), "+f"(c[2]), "+f"(c[3])
        : "r"(a.x), "r"(a.y), "r"(a.z), "r"(a.w), "r"(b0), "r"(b1));
}

// ---------------------------------------------------------------------------
// Prep: compute g, then write mma A-fragment tables (hi/lo bf16, rn split).
// ---------------------------------------------------------------------------
__global__ void prep_kernel(const float* __restrict__ filt) {
    __shared__ float tw_re[CCH], tw_im[CCH];
    __shared__ float inv_re[CCH], inv_im[CCH];
    __shared__ float ft[SCOPE];
    __shared__ float gh_s[CCH], gl_s[CCH];
    int t = threadIdx.x;   // 0..255
    if (t < SCOPE) ft[t] = filt[t];
    if (t < CCH) {
        float s, c;
        sincosf(6.283185307179586f * (float)t / 128.0f, &s, &c);
        tw_re[t] = c; tw_im[t] = s;
    }
    __syncthreads();
    if (t < CCH) {
        float fr = 1.0f, fi = 0.0f;
#pragma unroll
        for (int j = 0; j < SCOPE; j++) {
            int p = (115 + j) & 127;
            int idx = (t * p) & 127;
            fr -= ft[j] * tw_re[idx];
            fi += ft[j] * tw_im[idx];
        }
        float d = fr * fr + fi * fi;
        inv_re[t] = fr / d; inv_im[t] = -fi / d;
    }
    __syncthreads();
    if (t < CCH) {
        float acc = 0.0f;
        for (int f = 0; f < CCH; f++) {
            int idx = (f * t) & 127;
            acc += tw_re[idx] * inv_re[f] - tw_im[idx] * inv_im[f];
        }
        float g = acc * (1.0f / 128.0f);
        g_vec[t] = g;
        __nv_bfloat16 gh = __float2bfloat16(g);
        gh_s[t] = __bfloat162float(gh);
        gl_s[t] = g - gh_s[t];
    }
    __syncthreads();

    for (int e = t; e < 8 * 8 * 32; e += 256) {
        int lane = e & 31;
        int ks   = (e >> 5) & 7;
        int mt   = e >> 8;
        int m = mt * 16 + (lane >> 2);
        int k = ks * 16 + 2 * (lane & 3);
        uint4 h, l;
        int d0 = (m - k) & 127;
        h.x = pack_bf16x2(gh_s[d0], gh_s[(d0 - 1) & 127]);
        l.x = pack_bf16x2(gl_s[d0], gl_s[(d0 - 1) & 127]);
        int d1 = (m + 8 - k) & 127;
        h.y = pack_bf16x2(gh_s[d1], gh_s[(d1 - 1) & 127]);
        l.y = pack_bf16x2(gl_s[d1], gl_s[(d1 - 1) & 127]);
        int d2 = (m - k - 8) & 127;
        h.z = pack_bf16x2(gh_s[d2], gh_s[(d2 - 1) & 127]);
        l.z = pack_bf16x2(gl_s[d2], gl_s[(d2 - 1) & 127]);
        h.w = h.x;   // (m+8)-(k+8) == m-k
        l.w = l.x;
        a_frag_h[e] = h;
        a_frag_l[e] = l;
    }
}

// ---------------------------------------------------------------------------
// GEMM: one CTA = 128 out-channels x 128 spatial cols, K=128.
// ---------------------------------------------------------------------------
__global__ void __launch_bounds__(NTHREADS, 2)
gemm_mma(const float* __restrict__ x, float* __restrict__ y) {
    extern __shared__ char smc[];
    const int tid  = threadIdx.x;
    const int wid  = tid >> 5;
    const int lane = tid & 31;
    const int warp_m = wid & 3;
    const int warp_n = wid >> 2;

    const int b     = blockIdx.x;
    const int batch = b >> 5;
    const int col0  = (b & 31) * NTILE;
    const float* xb = x + (size_t)batch * CCH * HWSZ + col0;
    float*       yb = y + (size_t)batch * CCH * HWSZ + col0;

    // ---- Load X tile, truncation hi/lo split, conflict-free STS.128 ----
    // pair p: n = p&127, oct = p>>7 (8 k's). lanes -> consecutive n.
    {
        const int n0 = tid & 127;
        char* dst_h = smc + SMEM_XH + (uint32_t)n0 * XPITCH_B;
        char* dst_l = smc + SMEM_XL + (uint32_t)n0 * XPITCH_B;
        const float* pbase = xb + n0;
#pragma unroll
        for (int j = 0; j < 8; j++) {
            int oct = (tid >> 7) + 2 * j;          // 0..15
            const float* p = pbase + (size_t)(oct * 8) * HWSZ;
            float v[8];
            uint32_t u[8];
#pragma unroll
            for (int i = 0; i < 8; i++) {
                v[i] = __ldg(p + (size_t)i * HWSZ);
                u[i] = __float_as_uint(v[i]);
            }
            uint4 hq;
            hq.x = prmt_hi16(u[0], u[1]);
            hq.y = prmt_hi16(u[2], u[3]);
            hq.z = prmt_hi16(u[4], u[5]);
            hq.w = prmt_hi16(u[6], u[7]);
            float l[8];
#pragma unroll
            for (int i = 0; i < 8; i++)
                l[i] = v[i] - __uint_as_float(u[i] & 0xFFFF0000u);
            uint4 lq;
            lq.x = pack_bf16x2(l[0], l[1]);
            lq.y = pack_bf16x2(l[2], l[3]);
            lq.z = pack_bf16x2(l[4], l[5]);
            lq.w = pack_bf16x2(l[6], l[7]);
            *reinterpret_cast<uint4*>(dst_h + oct * 16) = hq;
            *reinterpret_cast<uint4*>(dst_l + oct * 16) = lq;
        }
    }
    __syncthreads();

    // ---- MMA mainloop (unchanged from R3) ----
    float acc[2][8][4];
#pragma unroll
    for (int mt = 0; mt < 2; mt++)
#pragma unroll
        for (int nt = 0; nt < 8; nt++)
#pragma unroll
            for (int r = 0; r < 4; r++) acc[mt][nt][r] = 0.0f;

    const uint32_t lm_off = ((lane & 7) + ((lane >> 4) << 3)) * XPITCH_B
                          + ((lane >> 3) & 1) * 16;
    const uint32_t xh_base = s2u(smc) + SMEM_XH + (uint32_t)warp_n * 64 * XPITCH_B + lm_off;
    const uint32_t xl_base = xh_base + SMEM_XL;
    const int fbase = (warp_m * 2) * 8 * 32 + lane;

#pragma unroll
    for (int ks = 0; ks < 8; ks++) {
        uint4 ah0 = a_frag_h[fbase + ks * 32];
        uint4 ah1 = a_frag_h[fbase + (8 + ks) * 32];
        uint4 al0 = a_frag_l[fbase + ks * 32];
        uint4 al1 = a_frag_l[fbase + (8 + ks) * 32];
        uint32_t kofs = ks * 32;
#pragma unroll
        for (int p = 0; p < 4; p++) {
            uint32_t bh0, bh1, bh2, bh3, bl0, bl1, bl2, bl3;
            ldsm_x4(bh0, bh1, bh2, bh3, xh_base + p * (16 * XPITCH_B) + kofs);
            ldsm_x4(bl0, bl1, bl2, bl3, xl_base + p * (16 * XPITCH_B) + kofs);
            mma16816(acc[0][2 * p],     ah0, bh0, bh1);
            mma16816(acc[1][2 * p],     ah1, bh0, bh1);
            mma16816(acc[0][2 * p + 1], ah0, bh2, bh3);
            mma16816(acc[1][2 * p + 1], ah1, bh2, bh3);
            mma16816(acc[0][2 * p],     al0, bh0, bh1);
            mma16816(acc[1][2 * p],     al1, bh0, bh1);
            mma16816(acc[0][2 * p + 1], al0, bh2, bh3);
            mma16816(acc[1][2 * p + 1], al1, bh2, bh3);
            mma16816(acc[0][2 * p],     ah0, bl0, bl1);
            mma16816(acc[1][2 * p],     ah1, bl0, bl1);
            mma16816(acc[0][2 * p + 1], ah0, bl2, bl3);
            mma16816(acc[1][2 * p + 1], ah1, bl2, bl3);
        }
    }

    // ---- Epilogue (unchanged) ----
#pragma unroll
    for (int mt = 0; mt < 2; mt++) {
        int m0 = warp_m * 32 + mt * 16 + (lane >> 2);
        float* yr0 = yb + (size_t)m0 * HWSZ;
        float* yr8 = yr0 + (size_t)8 * HWSZ;
#pragma unroll
        for (int nt = 0; nt < 8; nt++) {
            int n = warp_n * 64 + nt * 8 + 2 * (lane & 3);
            *reinterpret_cast<float2*>(yr0 + n) =
                make_float2(acc[mt][nt][0], acc[mt][nt][1]);
            *reinterpret_cast<float2*>(yr8 + n) =
                make_float2(acc[mt][nt][2], acc[mt][nt][3]);
        }
    }
}

// ---------------------------------------------------------------------------
extern "C" void kernel_launch(void* const* d_in, const int* in_sizes, int n_in,
                              void* d_out, int out_size) {
    const float* act  = (const float*)d_in[0];
    const float* filt = (const float*)d_in[1];
    if (n_in >= 2 && in_sizes[0] == SCOPE) {
        act  = (const float*)d_in[1];
        filt = (const float*)d_in[0];
    }
    float* out = (float*)d_out;

    prep_kernel<<<1, 256>>>(filt);

    cudaFuncSetAttribute(gemm_mma,
                         cudaFuncAttributeMaxDynamicSharedMemorySize, SMEM_DYN);
    gemm_mma<<<NBATCH * (HWSZ / NTILE), NTHREADS, SMEM_DYN>>>(act, out);
}

// round 5
// speedup vs baseline: 3.0164x; 1.0768x over previous
#include <cuda_runtime.h>
#include <cuda_fp16.h>
#include <cuda_bf16.h>
#include <cstdint>
#include <math.h>

// ConvergedInhibition == circular deconvolution along C=128 channels.
// Y = G @ X, G[r][j] = g[(r-j)&127], g = ifft(1/fft(delta-k)).
// R5: 2-pass fp16 split: Y = G16@Xh + G16@Xl, X = Xh+Xl exact fp16 split.
//     Warp tile 64m x 32n (balanced ldsm / A-frag traffic).

#define CCH     128
#define HWSZ    4096
#define NBATCH  64
#define SCOPE   27
#define NTILE   128
#define NTHREADS 256

#define XPITCH_B 272                       // bytes per n-row (17*16B)
#define SMEM_XH  0
#define SMEM_XL  (NTILE * XPITCH_B)        // 34816
#define SMEM_DYN (2 * NTILE * XPITCH_B)    // 69632

__device__ float g_vec[CCH];
__device__ uint4 a_frag[8 * 8 * 32];       // [mtile][kstep][lane], fp16 G, 16KB

// ---------------------------------------------------------------------------
__device__ __forceinline__ uint32_t s2u(const void* p) {
    uint32_t a;
    asm("{ .reg .u64 t; cvta.to.shared.u64 t, %1; cvt.u32.u64 %0, t; }"
        : "=r"(a) : "l"(p));
    return a;
}
__device__ __forceinline__ uint32_t pack_f16x2(float lo, float hi) {
    uint32_t r;
    asm("cvt.rn.f16x2.f32 %0, %1, %2;" : "=r"(r) : "f"(hi), "f"(lo));
    return r;
}
__device__ __forceinline__ void ldsm_x4(uint32_t& r0, uint32_t& r1,
                                        uint32_t& r2, uint32_t& r3, uint32_t a) {
    asm volatile("ldmatrix.sync.aligned.m8n8.x4.shared.b16 {%0,%1,%2,%3}, [%4];"
                 : "=r"(r0), "=r"(r1), "=r"(r2), "=r"(r3) : "r"(a));
}
__device__ __forceinline__ void mma16816(float* c, const uint4& a,
                                         uint32_t b0, uint32_t b1) {
    asm volatile(
        "mma.sync.aligned.m16n8k16.row.col.f32.f16.f16.f32 "
        "{%0,%1,%2,%3}, {%4,%5,%6,%7}, {%8,%9}, {%0,%1,%2,%3};"
        : "+f"(c[0]), "+f"(c[1]), "+f"(c[2]), "+f"(c[3])
        : "r"(a.x), "r"(a.y), "r"(a.z), "r"(a.w), "r"(b0), "r"(b1));
}

// ---------------------------------------------------------------------------
// Prep: compute g (validated R1), write fp16 mma A-fragment table.
// A frag regs (m16n8k16 row-major A): r0:(m,k) r1:(m+8,k) r2:(m,k+8)
// r3:(m+8,k+8); each reg = f16x2 of columns (k, k+1).
// ---------------------------------------------------------------------------
__global__ void prep_kernel(const float* __restrict__ filt) {
    __shared__ float tw_re[CCH], tw_im[CCH];
    __shared__ float inv_re[CCH], inv_im[CCH];
    __shared__ float ft[SCOPE];
    __shared__ float g_s[CCH];
    int t = threadIdx.x;   // 0..255
    if (t < SCOPE) ft[t] = filt[t];
    if (t < CCH) {
        float s, c;
        sincosf(6.283185307179586f * (float)t / 128.0f, &s, &c);
        tw_re[t] = c; tw_im[t] = s;
    }
    __syncthreads();
    if (t < CCH) {
        float fr = 1.0f, fi = 0.0f;
#pragma unroll
        for (int j = 0; j < SCOPE; j++) {
            int p = (115 + j) & 127;
            int idx = (t * p) & 127;
            fr -= ft[j] * tw_re[idx];
            fi += ft[j] * tw_im[idx];
        }
        float d = fr * fr + fi * fi;
        inv_re[t] = fr / d; inv_im[t] = -fi / d;
    }
    __syncthreads();
    if (t < CCH) {
        float acc = 0.0f;
        for (int f = 0; f < CCH; f++) {
            int idx = (f * t) & 127;
            acc += tw_re[idx] * inv_re[f] - tw_im[idx] * inv_im[f];
        }
        float g = acc * (1.0f / 128.0f);
        g_vec[t] = g;
        g_s[t] = g;
    }
    __syncthreads();

    for (int e = t; e < 8 * 8 * 32; e += 256) {
        int lane = e & 31;
        int ks   = (e >> 5) & 7;
        int mt   = e >> 8;
        int m = mt * 16 + (lane >> 2);
        int k = ks * 16 + 2 * (lane & 3);
        uint4 h;
        int d0 = (m - k) & 127;
        h.x = pack_f16x2(g_s[d0], g_s[(d0 - 1) & 127]);
        int d1 = (m + 8 - k) & 127;
        h.y = pack_f16x2(g_s[d1], g_s[(d1 - 1) & 127]);
        int d2 = (m - k - 8) & 127;
        h.z = pack_f16x2(g_s[d2], g_s[(d2 - 1) & 127]);
        h.w = h.x;   // (m+8)-(k+8) == m-k
        a_frag[e] = h;
    }
}

// ---------------------------------------------------------------------------
// GEMM: one CTA = 128 out-channels x 128 spatial cols, K=128.
// 8 warps: warp_m = wid&1 (64 rows), warp_n = wid>>1 (32 cols).
// ---------------------------------------------------------------------------
__global__ void __launch_bounds__(NTHREADS, 2)
gemm_mma(const float* __restrict__ x, float* __restrict__ y) {
    extern __shared__ char smc[];
    const int tid  = threadIdx.x;
    const int wid  = tid >> 5;
    const int lane = tid & 31;
    const int warp_m = wid & 1;
    const int warp_n = wid >> 1;

    const int b     = blockIdx.x;
    const int batch = b >> 5;
    const int col0  = (b & 31) * NTILE;
    const float* xb = x + (size_t)batch * CCH * HWSZ + col0;
    float*       yb = y + (size_t)batch * CCH * HWSZ + col0;

    // ---- Load X tile, exact fp16 hi/lo split, conflict-free STS.128 ----
    {
        const int n0 = tid & 127;
        char* dst_h = smc + SMEM_XH + (uint32_t)n0 * XPITCH_B;
        char* dst_l = smc + SMEM_XL + (uint32_t)n0 * XPITCH_B;
        const float* pbase = xb + n0;
#pragma unroll
        for (int j = 0; j < 8; j++) {
            int oct = (tid >> 7) + 2 * j;          // 0..15
            const float* p = pbase + (size_t)(oct * 8) * HWSZ;
            float v[8];
#pragma unroll
            for (int i = 0; i < 8; i++) v[i] = __ldg(p + (size_t)i * HWSZ);
            uint4 hq;
            hq.x = pack_f16x2(v[0], v[1]);
            hq.y = pack_f16x2(v[2], v[3]);
            hq.z = pack_f16x2(v[4], v[5]);
            hq.w = pack_f16x2(v[6], v[7]);
            // residuals: l = v - (float)f16(v), exact in fp32
            float l[8];
            {
                __half2 t0 = *reinterpret_cast<__half2*>(&hq.x);
                __half2 t1 = *reinterpret_cast<__half2*>(&hq.y);
                __half2 t2 = *reinterpret_cast<__half2*>(&hq.z);
                __half2 t3 = *reinterpret_cast<__half2*>(&hq.w);
                float2 f0 = __half22float2(t0);
                float2 f1 = __half22float2(t1);
                float2 f2 = __half22float2(t2);
                float2 f3 = __half22float2(t3);
                l[0] = v[0] - f0.x; l[1] = v[1] - f0.y;
                l[2] = v[2] - f1.x; l[3] = v[3] - f1.y;
                l[4] = v[4] - f2.x; l[5] = v[5] - f2.y;
                l[6] = v[6] - f3.x; l[7] = v[7] - f3.y;
            }
            uint4 lq;
            lq.x = pack_f16x2(l[0], l[1]);
            lq.y = pack_f16x2(l[2], l[3]);
            lq.z = pack_f16x2(l[4], l[5]);
            lq.w = pack_f16x2(l[6], l[7]);
            *reinterpret_cast<uint4*>(dst_h + oct * 16) = hq;
            *reinterpret_cast<uint4*>(dst_l + oct * 16) = lq;
        }
    }
    __syncthreads();

    // ---- MMA mainloop: 4 mtiles x 4 ntiles, 2 passes (Xh, Xl) ----
    float acc[4][4][4];
#pragma unroll
    for (int mt = 0; mt < 4; mt++)
#pragma unroll
        for (int nt = 0; nt < 4; nt++)
#pragma unroll
            for (int r = 0; r < 4; r++) acc[mt][nt][r] = 0.0f;

    const uint32_t lm_off = ((lane & 7) + ((lane >> 4) << 3)) * XPITCH_B
                          + ((lane >> 3) & 1) * 16;
    const uint32_t xh_base = s2u(smc) + SMEM_XH
                           + (uint32_t)warp_n * 32 * XPITCH_B + lm_off;
    const uint32_t xl_base = xh_base + SMEM_XL;
    const int fbase = (warp_m * 4) * 8 * 32 + lane;   // first of 4 mtiles

#pragma unroll
    for (int ks = 0; ks < 8; ks++) {
        uint4 a0 = a_frag[fbase + (0 * 8 + ks) * 32];
        uint4 a1 = a_frag[fbase + (1 * 8 + ks) * 32];
        uint4 a2 = a_frag[fbase + (2 * 8 + ks) * 32];
        uint4 a3 = a_frag[fbase + (3 * 8 + ks) * 32];
        uint32_t kofs = ks * 32;
#pragma unroll
        for (int p = 0; p < 2; p++) {
            uint32_t bh0, bh1, bh2, bh3, bl0, bl1, bl2, bl3;
            ldsm_x4(bh0, bh1, bh2, bh3, xh_base + p * (16 * XPITCH_B) + kofs);
            ldsm_x4(bl0, bl1, bl2, bl3, xl_base + p * (16 * XPITCH_B) + kofs);
            // ntile 2p: (b0,b1); ntile 2p+1: (b2,b3)
            mma16816(acc[0][2 * p],     a0, bh0, bh1);
            mma16816(acc[1][2 * p],     a1, bh0, bh1);
            mma16816(acc[2][2 * p],     a2, bh0, bh1);
            mma16816(acc[3][2 * p],     a3, bh0, bh1);
            mma16816(acc[0][2 * p + 1], a0, bh2, bh3);
            mma16816(acc[1][2 * p + 1], a1, bh2, bh3);
            mma16816(acc[2][2 * p + 1], a2, bh2, bh3);
            mma16816(acc[3][2 * p + 1], a3, bh2, bh3);
            mma16816(acc[0][2 * p],     a0, bl0, bl1);
            mma16816(acc[1][2 * p],     a1, bl0, bl1);
            mma16816(acc[2][2 * p],     a2, bl0, bl1);
            mma16816(acc[3][2 * p],     a3, bl0, bl1);
            mma16816(acc[0][2 * p + 1], a0, bl2, bl3);
            mma16816(acc[1][2 * p + 1], a1, bl2, bl3);
            mma16816(acc[2][2 * p + 1], a2, bl2, bl3);
            mma16816(acc[3][2 * p + 1], a3, bl2, bl3);
        }
    }

    // ---- Epilogue: c0,c1 at (m=lane/4, n=2*(lane&3)); c2,c3 at m+8 ----
#pragma unroll
    for (int mt = 0; mt < 4; mt++) {
        int m0 = warp_m * 64 + mt * 16 + (lane >> 2);
        float* yr0 = yb + (size_t)m0 * HWSZ;
        float* yr8 = yr0 + (size_t)8 * HWSZ;
#pragma unroll
        for (int nt = 0; nt < 4; nt++) {
            int n = warp_n * 32 + nt * 8 + 2 * (lane & 3);
            *reinterpret_cast<float2*>(yr0 + n) =
                make_float2(acc[mt][nt][0], acc[mt][nt][1]);
            *reinterpret_cast<float2*>(yr8 + n) =
                make_float2(acc[mt][nt][2], acc[mt][nt][3]);
        }
    }
}

// ---------------------------------------------------------------------------
extern "C" void kernel_launch(void* const* d_in, const int* in_sizes, int n_in,
                              void* d_out, int out_size) {
    const float* act  = (const float*)d_in[0];
    const float* filt = (const float*)d_in[1];
    if (n_in >= 2 && in_sizes[0] == SCOPE) {
        act  = (const float*)d_in[1];
        filt = (const float*)d_in[0];
    }
    float* out = (float*)d_out;

    prep_kernel<<<1, 256>>>(filt);

    cudaFuncSetAttribute(gemm_mma,
                         cudaFuncAttributeMaxDynamicSharedMemorySize, SMEM_DYN);
    gemm_mma<<<NBATCH * (HWSZ / NTILE), NTHREADS, SMEM_DYN>>>(act, out);
}